// round 6
// baseline (speedup 1.0000x reference)
#include <cuda_runtime.h>

#define NT 128
#define BB 256
#define SS 512

__device__ float g_expT[NT * NT];
__device__ float g_part[BB];
__device__ float g_gold[BB];
__device__ int   g_tags64;   // 1 if tags are int64, 0 if int32
__device__ int   g_mask4;    // 1 if mask is 4-byte, 0 if 1-byte

// Detect actual element widths of tags/mask (JAX x64-disabled silently makes
// int64 -> int32). Deterministic given fixed inputs; graph-capturable.
__global__ void detect_kernel(const void* tags, const void* mask) {
    if (threadIdx.x == 0) {
        const unsigned int* tw = (const unsigned int*)tags;
        int is64 = 1;
        for (int k = 0; k < 32; k++)
            if (tw[2 * k + 1] != 0u) is64 = 0;   // high words nonzero -> int32
        g_tags64 = is64;
        unsigned int w0 = ((const unsigned int*)mask)[0];
        g_mask4 = (w0 & 0xFFFFFF00u) ? 0 : 1;    // packed bytes -> 1-byte mask
    }
}

// Precompute exp(T) once per launch (cheap: 16K elements).
__global__ void expT_kernel(const float* __restrict__ T) {
    int idx = blockIdx.x * blockDim.x + threadIdx.x;
    g_expT[idx] = __expf(T[idx]);
}

// One CTA per batch. Thread j owns tag column j; expT[:,j] lives in registers.
__global__ __launch_bounds__(128, 2) void crf_forward_kernel(
    const float* __restrict__ emissions,      // [B, S, NT]
    const void* __restrict__ tags_raw,        // [B, S] int32 or int64
    const void* __restrict__ mask_raw,        // [B, S] 1B or 4B bool
    const float* __restrict__ trans)          // [NT, NT]
{
    const int b = blockIdx.x;
    const int j = threadIdx.x;
    const int lane = j & 31;
    const int wid = j >> 5;

    __shared__ float vsh[NT];
    __shared__ float warpred[4];
    __shared__ float warpsum[4];

    // ---- load exp(T) column j into registers (coalesced across threads) ----
    float eT[NT];
#pragma unroll
    for (int i = 0; i < NT; i++) eT[i] = g_expT[i * NT + j];

    const float* e_ptr = emissions + (size_t)b * SS * NT;
    float alpha = e_ptr[j];            // alpha0 = emissions[b, 0, :]
    e_ptr += NT;

    // ---- forward recursion, 511 steps ----
    for (int t = 1; t < SS; t++) {
        float e = e_ptr[j];            // emissions[b, t, j]
        e_ptr += NT;

        // block-wide max of alpha
        float wm = alpha;
#pragma unroll
        for (int o = 16; o; o >>= 1)
            wm = fmaxf(wm, __shfl_xor_sync(0xffffffffu, wm, o));
        if (lane == 0) warpred[wid] = wm;
        __syncthreads();
        float m = fmaxf(fmaxf(warpred[0], warpred[1]),
                        fmaxf(warpred[2], warpred[3]));

        vsh[j] = __expf(alpha - m);
        __syncthreads();

        // w[j] = sum_i v[i] * expT[i][j]  (v broadcast via float4, expT in regs)
        float a0 = 0.f, a1 = 0.f, a2 = 0.f, a3 = 0.f;
        const float4* v4 = (const float4*)vsh;
#pragma unroll
        for (int i = 0; i < NT / 4; i++) {
            float4 v = v4[i];
            a0 = fmaf(v.x, eT[4 * i + 0], a0);
            a1 = fmaf(v.y, eT[4 * i + 1], a1);
            a2 = fmaf(v.z, eT[4 * i + 2], a2);
            a3 = fmaf(v.w, eT[4 * i + 3], a3);
        }
        alpha = m + __logf((a0 + a1) + (a2 + a3)) + e;
    }

    // ---- partition contribution: logsumexp over final alpha ----
    {
        float wm = alpha;
#pragma unroll
        for (int o = 16; o; o >>= 1)
            wm = fmaxf(wm, __shfl_xor_sync(0xffffffffu, wm, o));
        if (lane == 0) warpred[wid] = wm;
        __syncthreads();
        float m = fmaxf(fmaxf(warpred[0], warpred[1]),
                        fmaxf(warpred[2], warpred[3]));
        float ex = __expf(alpha - m);
#pragma unroll
        for (int o = 16; o; o >>= 1)
            ex += __shfl_xor_sync(0xffffffffu, ex, o);
        if (lane == 0) warpsum[wid] = ex;
        __syncthreads();
        if (j == 0) {
            float s = (warpsum[0] + warpsum[1]) + (warpsum[2] + warpsum[3]);
            g_part[b] = m + __logf(s);
        }
    }

    // ---- gold score for this batch (dtype-adaptive tag/mask reads) ----
    {
        const int tags64 = g_tags64;
        const int mask4 = g_mask4;
        const long long* tg64 = (const long long*)tags_raw + (size_t)b * SS;
        const int* tg32 = (const int*)tags_raw + (size_t)b * SS;
        const int* mk32 = (const int*)mask_raw + (size_t)b * SS;
        const unsigned char* mk8 = (const unsigned char*)mask_raw + (size_t)b * SS;
        const float* em_row = emissions + (size_t)b * SS * NT;

        float g = 0.f;
        for (int t = j; t < SS; t += NT) {
            int tg = tags64 ? (int)tg64[t] : tg32[t];
            int mraw = mask4 ? mk32[t] : (int)mk8[t];
            float mk = mraw ? 1.f : 0.f;
            g += em_row[(size_t)t * NT + tg] * mk;
            if (t > 0) {
                int tp = tags64 ? (int)tg64[t - 1] : tg32[t - 1];
                g += trans[tp * NT + tg] * mk;
            }
        }
#pragma unroll
        for (int o = 16; o; o >>= 1)
            g += __shfl_xor_sync(0xffffffffu, g, o);
        __syncthreads();   // warpred free for reuse after this
        if (lane == 0) warpred[wid] = g;
        __syncthreads();
        if (j == 0)
            g_gold[b] = (warpred[0] + warpred[1]) + (warpred[2] + warpred[3]);
    }
}

// Deterministic final reduction: out = sum_b (part[b] - gold[b]).
__global__ void finish_kernel(float* __restrict__ out) {
    const int b = threadIdx.x;         // 256 threads
    const int lane = b & 31;
    const int wid = b >> 5;
    __shared__ float wsum[8];
    float v = g_part[b] - g_gold[b];
#pragma unroll
    for (int o = 16; o; o >>= 1)
        v += __shfl_xor_sync(0xffffffffu, v, o);
    if (lane == 0) wsum[wid] = v;
    __syncthreads();
    if (b == 0) {
        float s = 0.f;
#pragma unroll
        for (int w = 0; w < 8; w++) s += wsum[w];
        out[0] = s;
    }
}

extern "C" void kernel_launch(void* const* d_in, const int* in_sizes, int n_in,
                              void* d_out, int out_size) {
    const float* emissions = (const float*)d_in[0];
    const void* tags = d_in[1];
    const void* mask = d_in[2];
    const float* trans = (const float*)d_in[3];
    float* out = (float*)d_out;

    detect_kernel<<<1, 32>>>(tags, mask);
    expT_kernel<<<NT, NT>>>(trans);
    crf_forward_kernel<<<BB, NT>>>(emissions, tags, mask, trans);
    finish_kernel<<<1, BB>>>(out);
}

// round 7
// speedup vs baseline: 1.3202x; 1.3202x over previous
#include <cuda_runtime.h>

#define NT 128
#define BB 256
#define SS 512

__device__ float g_expT[NT * NT];
__device__ float g_part[BB];
__device__ float g_gold[BB];
__device__ int   g_tags64;   // 1 if tags are int64, 0 if int32
__device__ int   g_mask4;    // 1 if mask is 4-byte, 0 if 1-byte

// ---- packed fp32x2 helpers (sm_100+; ptxas never auto-fuses these) ----
__device__ __forceinline__ unsigned long long pack2(float lo, float hi) {
    unsigned long long r;
    asm("mov.b64 %0, {%1, %2};" : "=l"(r) : "f"(lo), "f"(hi));
    return r;
}
#define FMA2(acc, a, b) \
    asm("fma.rn.f32x2 %0, %1, %2, %0;" : "+l"(acc) : "l"(a), "l"(b))
__device__ __forceinline__ unsigned long long add2(unsigned long long a,
                                                   unsigned long long b) {
    unsigned long long d;
    asm("add.rn.f32x2 %0, %1, %2;" : "=l"(d) : "l"(a), "l"(b));
    return d;
}
__device__ __forceinline__ float hadd2(unsigned long long a) {
    float lo, hi;
    asm("mov.b64 {%0, %1}, %2;" : "=f"(lo), "=f"(hi) : "l"(a));
    return lo + hi;
}

// Detect actual element widths of tags/mask (JAX x64-disabled silently makes
// int64 -> int32). Deterministic given fixed inputs; graph-capturable.
__global__ void detect_kernel(const void* tags, const void* mask) {
    if (threadIdx.x == 0) {
        const unsigned int* tw = (const unsigned int*)tags;
        int is64 = 1;
        for (int k = 0; k < 32; k++)
            if (tw[2 * k + 1] != 0u) is64 = 0;   // high words nonzero -> int32
        g_tags64 = is64;
        unsigned int w0 = ((const unsigned int*)mask)[0];
        g_mask4 = (w0 & 0xFFFFFF00u) ? 0 : 1;    // packed bytes -> 1-byte mask
    }
}

// Precompute exp(T) once per launch (cheap: 16K elements).
__global__ void expT_kernel(const float* __restrict__ T) {
    int idx = blockIdx.x * blockDim.x + threadIdx.x;
    g_expT[idx] = __expf(T[idx]);
}

// One CTA per batch. Thread j owns tag column j; expT[:,j] packed in 64 regs.
__global__ __launch_bounds__(128, 2) void crf_forward_kernel(
    const float* __restrict__ emissions,      // [B, S, NT]
    const void* __restrict__ tags_raw,        // [B, S] int32 or int64
    const void* __restrict__ mask_raw,        // [B, S] 1B or 4B bool
    const float* __restrict__ trans)          // [NT, NT]
{
    const int b = blockIdx.x;
    const int j = threadIdx.x;
    const int lane = j & 31;
    const int wid = j >> 5;

    __shared__ __align__(16) float vsh[2][NT];
    __shared__ float msh[2];
    __shared__ float warpred[4];
    __shared__ float warpsum[4];

    // ---- pack exp(T) column j: eTp[i] = (expT[2i][j], expT[2i+1][j]) ----
    unsigned long long eTp[NT / 2];
#pragma unroll
    for (int i = 0; i < NT / 2; i++)
        eTp[i] = pack2(g_expT[(2 * i) * NT + j], g_expT[(2 * i + 1) * NT + j]);

    const float* e_ptr = emissions + (size_t)b * SS * NT;
    float alpha = e_ptr[j];            // alpha0 = emissions[b, 0, :]
    e_ptr += NT;

    // initial surrogate max: alpha0[0]
    if (j == 0) msh[0] = alpha;
    __syncthreads();
    float m = msh[0];                  // stale-by-one surrogate shift

    float e_cur = e_ptr[j];            // emissions[b, 1, j]
    e_ptr += NT;

    // ---- forward recursion, 511 steps; ONE sync per step ----
    int buf = 0;
    for (int t = 1; t < SS; t++) {
        // prefetch next emission row (hides DRAM latency behind the FMA loop)
        float e_nxt = 0.f;
        if (t < SS - 1) { e_nxt = e_ptr[j]; e_ptr += NT; }

        vsh[buf][j] = __expf(alpha - m);
        if (j == 0) msh[buf] = alpha;  // broadcast alpha_t[0] for step t+1
        __syncthreads();
        float m_next = msh[buf];

        // w[j] = sum_i v[i] * expT[i][j], packed 2-wide
        unsigned long long acc0 = 0ull, acc1 = 0ull, acc2 = 0ull, acc3 = 0ull;
        const ulonglong2* v2 = (const ulonglong2*)vsh[buf];
#pragma unroll
        for (int i = 0; i < NT / 4; i += 2) {
            ulonglong2 va = v2[i];
            ulonglong2 vb = v2[i + 1];
            FMA2(acc0, va.x, eTp[2 * i + 0]);
            FMA2(acc1, va.y, eTp[2 * i + 1]);
            FMA2(acc2, vb.x, eTp[2 * i + 2]);
            FMA2(acc3, vb.y, eTp[2 * i + 3]);
        }
        float w = hadd2(add2(add2(acc0, acc1), add2(acc2, acc3)));

        alpha = m + __logf(w) + e_cur; // must use the SAME m as the exp
        m = m_next;
        e_cur = e_nxt;
        buf ^= 1;
    }

    // ---- partition contribution: exact logsumexp over final alpha ----
    {
        float wm = alpha;
#pragma unroll
        for (int o = 16; o; o >>= 1)
            wm = fmaxf(wm, __shfl_xor_sync(0xffffffffu, wm, o));
        if (lane == 0) warpred[wid] = wm;
        __syncthreads();
        float mx = fmaxf(fmaxf(warpred[0], warpred[1]),
                         fmaxf(warpred[2], warpred[3]));
        float ex = __expf(alpha - mx);
#pragma unroll
        for (int o = 16; o; o >>= 1)
            ex += __shfl_xor_sync(0xffffffffu, ex, o);
        if (lane == 0) warpsum[wid] = ex;
        __syncthreads();
        if (j == 0) {
            float s = (warpsum[0] + warpsum[1]) + (warpsum[2] + warpsum[3]);
            g_part[b] = mx + __logf(s);
        }
    }

    // ---- gold score for this batch (dtype-adaptive tag/mask reads) ----
    {
        const int tags64 = g_tags64;
        const int mask4 = g_mask4;
        const long long* tg64 = (const long long*)tags_raw + (size_t)b * SS;
        const int* tg32 = (const int*)tags_raw + (size_t)b * SS;
        const int* mk32 = (const int*)mask_raw + (size_t)b * SS;
        const unsigned char* mk8 = (const unsigned char*)mask_raw + (size_t)b * SS;
        const float* em_row = emissions + (size_t)b * SS * NT;

        float g = 0.f;
        for (int t = j; t < SS; t += NT) {
            int tg = tags64 ? (int)tg64[t] : tg32[t];
            int mraw = mask4 ? mk32[t] : (int)mk8[t];
            float mk = mraw ? 1.f : 0.f;
            g += em_row[(size_t)t * NT + tg] * mk;
            if (t > 0) {
                int tp = tags64 ? (int)tg64[t - 1] : tg32[t - 1];
                g += trans[tp * NT + tg] * mk;
            }
        }
#pragma unroll
        for (int o = 16; o; o >>= 1)
            g += __shfl_xor_sync(0xffffffffu, g, o);
        __syncthreads();   // warpred free for reuse after this
        if (lane == 0) warpred[wid] = g;
        __syncthreads();
        if (j == 0)
            g_gold[b] = (warpred[0] + warpred[1]) + (warpred[2] + warpred[3]);
    }
}

// Deterministic final reduction: out = sum_b (part[b] - gold[b]).
__global__ void finish_kernel(float* __restrict__ out) {
    const int b = threadIdx.x;         // 256 threads
    const int lane = b & 31;
    const int wid = b >> 5;
    __shared__ float wsum[8];
    float v = g_part[b] - g_gold[b];
#pragma unroll
    for (int o = 16; o; o >>= 1)
        v += __shfl_xor_sync(0xffffffffu, v, o);
    if (lane == 0) wsum[wid] = v;
    __syncthreads();
    if (b == 0) {
        float s = 0.f;
#pragma unroll
        for (int w = 0; w < 8; w++) s += wsum[w];
        out[0] = s;
    }
}

extern "C" void kernel_launch(void* const* d_in, const int* in_sizes, int n_in,
                              void* d_out, int out_size) {
    const float* emissions = (const float*)d_in[0];
    const void* tags = d_in[1];
    const void* mask = d_in[2];
    const float* trans = (const float*)d_in[3];
    float* out = (float*)d_out;

    detect_kernel<<<1, 32>>>(tags, mask);
    expT_kernel<<<NT, NT>>>(trans);
    crf_forward_kernel<<<BB, NT>>>(emissions, tags, mask, trans);
    finish_kernel<<<1, BB>>>(out);
}